// round 1
// baseline (speedup 1.0000x reference)
#include <cuda_runtime.h>
#include <math.h>

#define N_NODES 10000
#define N_PAD   10112          // 79 * 128
#define E_EDGES 160000
#define D_IN    256
#define H1      128
#define H2      64
#define NT      79             // decoder tiles per dim

// ---------------- scratch (device globals; zero-init at load) ----------------
__device__ float g_dis [N_NODES];          // degree, then rsqrt(degree)
__device__ float g_hw1 [N_PAD * H1];       // x @ W1
__device__ float g_h1  [N_PAD * H1];       // layer-1 aggregated (pre-relu)
__device__ float g_hw23[N_PAD * H1];       // [h@W2 | h@W3]
__device__ float g_mls [N_PAD * H1];       // [mean | log_std] aggregated
__device__ float g_z   [N_PAD * H2];       // latent (pad rows zeroed)

// ---------------- degree / normalization ----------------
__global__ void k_deg_init() {
    int i = blockIdx.x * 256 + threadIdx.x;
    if (i < N_NODES) g_dis[i] = 1.0f;                     // self-loop weight
}
__global__ void k_deg_edges(const int* __restrict__ ei, const float* __restrict__ ew) {
    int e = blockIdx.x * 256 + threadIdx.x;
    if (e < E_EDGES) atomicAdd(&g_dis[ei[E_EDGES + e]], ew[e]);   // segment by col
}
__global__ void k_dis() {
    int i = blockIdx.x * 256 + threadIdx.x;
    if (i < N_NODES) g_dis[i] = rsqrtf(g_dis[i]);         // deg >= 1 always
}

// ---------------- shared f32x2 inner product over a 32-K chunk ----------------
// As layout: [rows][36] (row-major, pad 36), Bs layout: [k][132] (n contiguous)
template<int TM>
__device__ __forceinline__ void mma32(const float* __restrict__ As,
                                      const float* __restrict__ Bs,
                                      int ty, int tx,
                                      unsigned long long (&acc)[TM][4]) {
#pragma unroll
    for (int k = 0; k < 32; k++) {
        unsigned long long b2[4];
#pragma unroll
        for (int jp = 0; jp < 4; jp++)
            b2[jp] = *reinterpret_cast<const unsigned long long*>(Bs + k * 132 + tx * 8 + jp * 2);
#pragma unroll
        for (int i = 0; i < TM; i++) {
            float a = As[(ty * TM + i) * 36 + k];
            unsigned long long ad;
            asm("mov.b64 %0, {%1, %1};" : "=l"(ad) : "f"(a));
#pragma unroll
            for (int jp = 0; jp < 4; jp++)
                asm("fma.rn.f32x2 %0, %1, %2, %0;" : "+l"(acc[i][jp]) : "l"(ad), "l"(b2[jp]));
        }
    }
}

// ---------------- GEMM1: g_hw1 = x @ W1   (M=10000, K=256, N=128) ----------------
__global__ __launch_bounds__(256) void k_gemm1(const float* __restrict__ x,
                                               const float* __restrict__ W1) {
    __shared__ float As[64 * 36];
    __shared__ float Bs[32 * 132];
    int tid = threadIdx.x, tx = tid & 15, ty = tid >> 4;
    int mb = blockIdx.x * 64;
    unsigned long long acc[4][4] = {};
    for (int kc = 0; kc < D_IN; kc += 32) {
#pragma unroll
        for (int r = 0; r < 2; r++) {                     // A tile 64x32
            int idx = tid + r * 256;
            int m = idx >> 3, k4 = idx & 7;
            float4 v = make_float4(0.f, 0.f, 0.f, 0.f);
            if (mb + m < N_NODES)
                v = *reinterpret_cast<const float4*>(x + (size_t)(mb + m) * D_IN + kc + k4 * 4);
            *reinterpret_cast<float4*>(As + m * 36 + k4 * 4) = v;
        }
#pragma unroll
        for (int r = 0; r < 4; r++) {                     // B tile 32x128
            int idx = tid + r * 256;
            int k = idx >> 5, n4 = idx & 31;
            float4 v = *reinterpret_cast<const float4*>(W1 + (size_t)(kc + k) * H1 + n4 * 4);
            *reinterpret_cast<float4*>(Bs + k * 132 + n4 * 4) = v;
        }
        __syncthreads();
        mma32<4>(As, Bs, ty, tx, acc);
        __syncthreads();
    }
#pragma unroll
    for (int i = 0; i < 4; i++) {
        int row = mb + ty * 4 + i;                        // padded scratch, no guard
        float c[8];
#pragma unroll
        for (int jp = 0; jp < 4; jp++)
            asm("mov.b64 {%0, %1}, %2;" : "=f"(c[jp*2]), "=f"(c[jp*2+1]) : "l"(acc[i][jp]));
        float4* p = reinterpret_cast<float4*>(g_hw1 + (size_t)row * H1 + tx * 8);
        p[0] = make_float4(c[0], c[1], c[2], c[3]);
        p[1] = make_float4(c[4], c[5], c[6], c[7]);
    }
}

// ---------------- GEMM23: g_hw23 = relu(g_h1) @ [W2 | W3]  (K=128, N=128) ----------------
__global__ __launch_bounds__(256) void k_gemm23(const float* __restrict__ W2,
                                                const float* __restrict__ W3) {
    __shared__ float As[64 * 36];
    __shared__ float Bs[32 * 132];
    int tid = threadIdx.x, tx = tid & 15, ty = tid >> 4;
    int mb = blockIdx.x * 64;
    unsigned long long acc[4][4] = {};
    for (int kc = 0; kc < H1; kc += 32) {
#pragma unroll
        for (int r = 0; r < 2; r++) {                     // A tile 64x32 (relu)
            int idx = tid + r * 256;
            int m = idx >> 3, k4 = idx & 7;
            float4 v = *reinterpret_cast<const float4*>(g_h1 + (size_t)(mb + m) * H1 + kc + k4 * 4);
            v.x = fmaxf(v.x, 0.f); v.y = fmaxf(v.y, 0.f);
            v.z = fmaxf(v.z, 0.f); v.w = fmaxf(v.w, 0.f);
            *reinterpret_cast<float4*>(As + m * 36 + k4 * 4) = v;
        }
#pragma unroll
        for (int r = 0; r < 4; r++) {                     // B: [W2 | W3]
            int idx = tid + r * 256;
            int k = idx >> 5, n4 = idx & 31;
            float4 v;
            if (n4 < 16)
                v = *reinterpret_cast<const float4*>(W2 + (size_t)(kc + k) * H2 + n4 * 4);
            else
                v = *reinterpret_cast<const float4*>(W3 + (size_t)(kc + k) * H2 + (n4 - 16) * 4);
            *reinterpret_cast<float4*>(Bs + k * 132 + n4 * 4) = v;
        }
        __syncthreads();
        mma32<4>(As, Bs, ty, tx, acc);
        __syncthreads();
    }
#pragma unroll
    for (int i = 0; i < 4; i++) {
        int row = mb + ty * 4 + i;
        float c[8];
#pragma unroll
        for (int jp = 0; jp < 4; jp++)
            asm("mov.b64 {%0, %1}, %2;" : "=f"(c[jp*2]), "=f"(c[jp*2+1]) : "l"(acc[i][jp]));
        float4* p = reinterpret_cast<float4*>(g_hw23 + (size_t)row * H1 + tx * 8);
        p[0] = make_float4(c[0], c[1], c[2], c[3]);
        p[1] = make_float4(c[4], c[5], c[6], c[7]);
    }
}

// ---------------- aggregation ----------------
// init: out = dis^2 * in + bias   (self-loop term + bias, full overwrite each call)
__global__ void k_agg_init(int layer, const float* __restrict__ b1,
                           const float* __restrict__ b2, const float* __restrict__ b3) {
    int idx = blockIdx.x * 256 + threadIdx.x;
    if (idx >= N_NODES * H1) return;
    int i = idx >> 7, f = idx & 127;
    float d = g_dis[i]; d = d * d;
    if (layer == 1) g_h1[idx]  = d * g_hw1[idx]  + b1[f];
    else            g_mls[idx] = d * g_hw23[idx] + (f < 64 ? b2[f] : b3[f - 64]);
}

// edges: out[col] += dis[row]*ew*dis[col] * in[row]  via red.global.add.v4.f32
__global__ void k_agg_edges(int layer, const int* __restrict__ ei, const float* __restrict__ ew) {
    int t = blockIdx.x * 256 + threadIdx.x;
    if (t >= E_EDGES * 32) return;
    int e = t >> 5, q = t & 31;
    int r = ei[e], c = ei[E_EDGES + e];
    float w = g_dis[r] * ew[e] * g_dis[c];
    const float* in = (layer == 1) ? g_hw1 : g_hw23;
    float*      out = (layer == 1) ? g_h1  : g_mls;
    float4 v = *reinterpret_cast<const float4*>(in + (size_t)r * H1 + q * 4);
    float* p = out + (size_t)c * H1 + q * 4;
    unsigned long long gp = (unsigned long long)__cvta_generic_to_global(p);
    asm volatile("red.global.add.v4.f32 [%0], {%1, %2, %3, %4};"
                 :: "l"(gp), "f"(w * v.x), "f"(w * v.y), "f"(w * v.z), "f"(w * v.w)
                 : "memory");
}

// ---------------- reparameterization: z = mean + noise * exp(log_std) ----------------
__global__ void k_z(const float* __restrict__ noise) {
    int idx = blockIdx.x * 256 + threadIdx.x;             // covers N_PAD * 64
    if (idx >= N_PAD * H2) return;
    int i = idx >> 6, f = idx & 63;
    float v = 0.f;
    if (i < N_NODES) {
        float mean = g_mls[i * H1 + f];
        float ls   = g_mls[i * H1 + 64 + f];
        v = mean + noise[idx] * expf(ls);
    }
    g_z[idx] = v;                                          // pad rows -> 0
}

// ---------------- decoder: out = sigmoid(z @ z^T), symmetric ----------------
__global__ __launch_bounds__(256) void k_decoder(float* __restrict__ out) {
    int bj = blockIdx.x, bi = blockIdx.y;
    if (bj < bi) return;                                   // upper triangle only
    __shared__ float As[128 * 36];
    __shared__ float Bs[32 * 132];
    int tid = threadIdx.x, tx = tid & 15, ty = tid >> 4;
    int rb = bi * 128, cb = bj * 128;
    unsigned long long acc[8][4] = {};
    for (int kc = 0; kc < H2; kc += 32) {
#pragma unroll
        for (int r = 0; r < 4; r++) {                      // A: z rows [rb..rb+128)
            int idx = tid + r * 256;
            int m = idx >> 3, k4 = idx & 7;
            float4 v = *reinterpret_cast<const float4*>(g_z + (size_t)(rb + m) * H2 + kc + k4 * 4);
            *reinterpret_cast<float4*>(As + m * 36 + k4 * 4) = v;
        }
#pragma unroll
        for (int r = 0; r < 4; r++) {                      // B: z rows [cb..cb+128), transposed
            int idx = tid + r * 256;
            int n = idx >> 3, k4 = idx & 7;
            float4 v = *reinterpret_cast<const float4*>(g_z + (size_t)(cb + n) * H2 + kc + k4 * 4);
            Bs[(k4 * 4 + 0) * 132 + n] = v.x;
            Bs[(k4 * 4 + 1) * 132 + n] = v.y;
            Bs[(k4 * 4 + 2) * 132 + n] = v.z;
            Bs[(k4 * 4 + 3) * 132 + n] = v.w;
        }
        __syncthreads();
        mma32<8>(As, Bs, ty, tx, acc);
        __syncthreads();
    }
    float c[8][8];
#pragma unroll
    for (int i = 0; i < 8; i++)
#pragma unroll
        for (int jp = 0; jp < 4; jp++)
            asm("mov.b64 {%0, %1}, %2;" : "=f"(c[i][jp*2]), "=f"(c[i][jp*2+1]) : "l"(acc[i][jp]));
    // sigmoid(x) = 1 / (1 + 2^(-x*log2e))
#pragma unroll
    for (int i = 0; i < 8; i++)
#pragma unroll
        for (int j = 0; j < 8; j++) {
            float e;
            asm("ex2.approx.f32 %0, %1;" : "=f"(e) : "f"(c[i][j] * -1.4426950408889634f));
            asm("rcp.approx.f32 %0, %1;" : "=f"(c[i][j]) : "f"(1.0f + e));
        }
    // direct tile
    bool fullC = (cb + 128 <= N_NODES);
#pragma unroll
    for (int i = 0; i < 8; i++) {
        int row = rb + ty * 8 + i;
        if (row < N_NODES) {
            float* p = out + (size_t)row * N_NODES + cb + tx * 8;
            if (fullC) {
                *reinterpret_cast<float4*>(p)     = make_float4(c[i][0], c[i][1], c[i][2], c[i][3]);
                *reinterpret_cast<float4*>(p + 4) = make_float4(c[i][4], c[i][5], c[i][6], c[i][7]);
            } else {
                int c0 = cb + tx * 8;
#pragma unroll
                for (int j = 0; j < 8; j++) if (c0 + j < N_NODES) p[j] = c[i][j];
            }
        }
    }
    // mirrored tile (transpose), skip on the diagonal
    if (bi != bj) {
        bool fullR = (rb + 128 <= N_NODES);
#pragma unroll
        for (int j = 0; j < 8; j++) {
            int row = cb + tx * 8 + j;
            if (row < N_NODES) {
                float* p = out + (size_t)row * N_NODES + rb + ty * 8;
                if (fullR) {
                    *reinterpret_cast<float4*>(p)     = make_float4(c[0][j], c[1][j], c[2][j], c[3][j]);
                    *reinterpret_cast<float4*>(p + 4) = make_float4(c[4][j], c[5][j], c[6][j], c[7][j]);
                } else {
                    int c0 = rb + ty * 8;
#pragma unroll
                    for (int ii = 0; ii < 8; ii++) if (c0 + ii < N_NODES) p[ii] = c[ii][j];
                }
            }
        }
    }
}

// ---------------- launch ----------------
extern "C" void kernel_launch(void* const* d_in, const int* in_sizes, int n_in,
                              void* d_out, int out_size) {
    const float* x     = (const float*)d_in[0];
    const int*   ei    = (const int*)  d_in[1];
    const float* ew    = (const float*)d_in[2];
    const float* noise = (const float*)d_in[3];
    const float* W1    = (const float*)d_in[4];
    const float* b1    = (const float*)d_in[5];
    const float* W2    = (const float*)d_in[6];
    const float* b2    = (const float*)d_in[7];
    const float* W3    = (const float*)d_in[8];
    const float* b3    = (const float*)d_in[9];
    float* out = (float*)d_out;

    k_deg_init <<<(N_NODES + 255) / 256, 256>>>();
    k_deg_edges<<<(E_EDGES + 255) / 256, 256>>>(ei, ew);
    k_dis      <<<(N_NODES + 255) / 256, 256>>>();

    k_gemm1    <<<157, 256>>>(x, W1);                       // 157*64 = 10048 rows
    k_agg_init <<<(N_NODES * H1) / 256, 256>>>(1, b1, b2, b3);
    k_agg_edges<<<(E_EDGES * 32) / 256, 256>>>(1, ei, ew);

    k_gemm23   <<<157, 256>>>(W2, W3);
    k_agg_init <<<(N_NODES * H1) / 256, 256>>>(2, b1, b2, b3);
    k_agg_edges<<<(E_EDGES * 32) / 256, 256>>>(2, ei, ew);

    k_z        <<<(N_PAD * H2) / 256, 256>>>(noise);

    dim3 g(NT, NT);
    k_decoder  <<<g, 256>>>(out);
}

// round 2
// speedup vs baseline: 1.0449x; 1.0449x over previous
#include <cuda_runtime.h>
#include <math.h>

typedef unsigned long long ull;

#define N_NODES 10000
#define N_PAD   10112          // 79 * 128
#define E_EDGES 160000
#define D_IN    256
#define H1      128
#define H2      64
#define NT      79
#define FULLM   0xFFFFFFFFu

// ---------------- scratch (device globals) ----------------
__device__ float g_dis [N_NODES];          // weighted degree -> rsqrt(degree)
__device__ int   g_cnt [N_NODES];          // edges per col
__device__ int   g_off [N_NODES];          // CSR starts
__device__ int   g_cur [N_NODES];          // scatter cursors
__device__ int   g_bsum[64];
__device__ int   g_boff[64];
__device__ int   g_crow[E_EDGES];          // CSR: src row
__device__ float g_cw  [E_EDGES];          // CSR: norm weight
__device__ float g_hw1 [N_PAD * H1];
__device__ float g_h1  [N_PAD * H1];
__device__ float g_hw23[N_PAD * H1];
__device__ float g_mls [N_PAD * H1];
__device__ float g_z   [N_PAD * H2];

// ---------------- degree / CSR build ----------------
__global__ void k_prep() {
    int i = blockIdx.x * 256 + threadIdx.x;
    if (i < N_NODES) { g_dis[i] = 1.0f; g_cnt[i] = 0; }
}
__global__ void k_deg_edges(const int* __restrict__ ei, const float* __restrict__ ew) {
    int e = blockIdx.x * 256 + threadIdx.x;
    if (e < E_EDGES) {
        int c = ei[E_EDGES + e];
        atomicAdd(&g_dis[c], ew[e]);
        atomicAdd(&g_cnt[c], 1);
    }
}
__global__ void k_dis() {
    int i = blockIdx.x * 256 + threadIdx.x;
    if (i < N_NODES) g_dis[i] = rsqrtf(g_dis[i]);
}
__global__ void k_bsum() {
    __shared__ int s[256];
    int t = threadIdx.x;
    int i = blockIdx.x * 256 + t;
    s[t] = (i < N_NODES) ? g_cnt[i] : 0;
    __syncthreads();
    for (int d = 128; d > 0; d >>= 1) {
        if (t < d) s[t] += s[t + d];
        __syncthreads();
    }
    if (t == 0) g_bsum[blockIdx.x] = s[0];
}
__global__ void k_scanb() {                           // 1 block, 64 threads
    __shared__ int s[64];
    int t = threadIdx.x;
    int v = (t < 40) ? g_bsum[t] : 0;
    s[t] = v; __syncthreads();
    for (int d = 1; d < 64; d <<= 1) {
        int x = (t >= d) ? s[t - d] : 0;
        __syncthreads();
        s[t] += x;
        __syncthreads();
    }
    if (t < 40) g_boff[t] = s[t] - v;                  // exclusive
}
__global__ void k_scan() {                             // 40 blocks x 256
    __shared__ int s[256];
    int t = threadIdx.x;
    int i = blockIdx.x * 256 + t;
    int v = (i < N_NODES) ? g_cnt[i] : 0;
    s[t] = v; __syncthreads();
    for (int d = 1; d < 256; d <<= 1) {
        int x = (t >= d) ? s[t - d] : 0;
        __syncthreads();
        s[t] += x;
        __syncthreads();
    }
    if (i < N_NODES) {
        int off = g_boff[blockIdx.x] + s[t] - v;       // exclusive
        g_off[i] = off;
        g_cur[i] = off;
    }
}
__global__ void k_scatter(const int* __restrict__ ei, const float* __restrict__ ew) {
    int e = blockIdx.x * 256 + threadIdx.x;
    if (e < E_EDGES) {
        int r = ei[e], c = ei[E_EDGES + e];
        int p = atomicAdd(&g_cur[c], 1);
        g_crow[p] = r;
        g_cw[p]   = g_dis[r] * ew[e] * g_dis[c];
    }
}

// ---------------- f32x2 inner product over a 32-K chunk ----------------
// As: [rows][36] floats; Bs: [k][132] floats, LDS.128 conflict-free B loads.
template<int TM>
__device__ __forceinline__ void mma32(const float* __restrict__ As,
                                      const float* __restrict__ Bs,
                                      int ty, int tx, ull (&acc)[TM][4]) {
#pragma unroll
    for (int k = 0; k < 32; k++) {
        ulonglong2 p0 = *reinterpret_cast<const ulonglong2*>(Bs + k * 132 + tx * 8);
        ulonglong2 p1 = *reinterpret_cast<const ulonglong2*>(Bs + k * 132 + tx * 8 + 4);
        ull b[4] = {p0.x, p0.y, p1.x, p1.y};
#pragma unroll
        for (int i = 0; i < TM; i++) {
            float a = As[(ty * TM + i) * 36 + k];
            ull ad;
            asm("mov.b64 %0, {%1, %1};" : "=l"(ad) : "f"(a));
#pragma unroll
            for (int jp = 0; jp < 4; jp++)
                asm("fma.rn.f32x2 %0, %1, %2, %0;" : "+l"(acc[i][jp]) : "l"(ad), "l"(b[jp]));
        }
    }
}

// ---------------- GEMM1: g_hw1 = x @ W1  (M=10000, K=256, N=128) ----------------
__global__ __launch_bounds__(256) void k_gemm1(const float* __restrict__ x,
                                               const float* __restrict__ W1) {
    __shared__ __align__(16) float As[64 * 36];
    __shared__ __align__(16) float Bs[32 * 132];
    int tid = threadIdx.x, tx = tid & 15, ty = tid >> 4;
    int mb = blockIdx.x * 64;
    float4 pa[2], pb[4];
#pragma unroll
    for (int r = 0; r < 2; r++) {                       // prefetch chunk 0 A
        int idx = tid + r * 256, m = idx >> 3, k4 = idx & 7;
        pa[r] = make_float4(0.f, 0.f, 0.f, 0.f);
        if (mb + m < N_NODES)
            pa[r] = *reinterpret_cast<const float4*>(x + (size_t)(mb + m) * D_IN + k4 * 4);
    }
#pragma unroll
    for (int r = 0; r < 4; r++) {                       // prefetch chunk 0 B
        int idx = tid + r * 256, kk = idx >> 5, n4 = idx & 31;
        pb[r] = *reinterpret_cast<const float4*>(W1 + (size_t)kk * H1 + n4 * 4);
    }
    ull acc[4][4] = {};
    for (int c = 0; c < 8; c++) {
#pragma unroll
        for (int r = 0; r < 2; r++) {
            int idx = tid + r * 256, m = idx >> 3, k4 = idx & 7;
            *reinterpret_cast<float4*>(As + m * 36 + k4 * 4) = pa[r];
        }
#pragma unroll
        for (int r = 0; r < 4; r++) {
            int idx = tid + r * 256, kk = idx >> 5, n4 = idx & 31;
            *reinterpret_cast<float4*>(Bs + kk * 132 + n4 * 4) = pb[r];
        }
        __syncthreads();
        if (c < 7) {
            int kc = (c + 1) * 32;
#pragma unroll
            for (int r = 0; r < 2; r++) {
                int idx = tid + r * 256, m = idx >> 3, k4 = idx & 7;
                pa[r] = make_float4(0.f, 0.f, 0.f, 0.f);
                if (mb + m < N_NODES)
                    pa[r] = *reinterpret_cast<const float4*>(x + (size_t)(mb + m) * D_IN + kc + k4 * 4);
            }
#pragma unroll
            for (int r = 0; r < 4; r++) {
                int idx = tid + r * 256, kk = idx >> 5, n4 = idx & 31;
                pb[r] = *reinterpret_cast<const float4*>(W1 + (size_t)(kc + kk) * H1 + n4 * 4);
            }
        }
        mma32<4>(As, Bs, ty, tx, acc);
        __syncthreads();
    }
#pragma unroll
    for (int i = 0; i < 4; i++) {
        int row = mb + ty * 4 + i;
        float cv[8];
#pragma unroll
        for (int jp = 0; jp < 4; jp++)
            asm("mov.b64 {%0, %1}, %2;" : "=f"(cv[jp*2]), "=f"(cv[jp*2+1]) : "l"(acc[i][jp]));
        float4* p = reinterpret_cast<float4*>(g_hw1 + (size_t)row * H1 + tx * 8);
        p[0] = make_float4(cv[0], cv[1], cv[2], cv[3]);
        p[1] = make_float4(cv[4], cv[5], cv[6], cv[7]);
    }
}

// ---------------- GEMM23: g_hw23 = relu(g_h1) @ [W2|W3]  (K=128, N=128) ----------------
__global__ __launch_bounds__(256) void k_gemm23(const float* __restrict__ W2,
                                                const float* __restrict__ W3) {
    __shared__ __align__(16) float As[64 * 36];
    __shared__ __align__(16) float Bs[32 * 132];
    int tid = threadIdx.x, tx = tid & 15, ty = tid >> 4;
    int mb = blockIdx.x * 64;
    float4 pa[2], pb[4];
#pragma unroll
    for (int r = 0; r < 2; r++) {
        int idx = tid + r * 256, m = idx >> 3, k4 = idx & 7;
        float4 v = *reinterpret_cast<const float4*>(g_h1 + (size_t)(mb + m) * H1 + k4 * 4);
        pa[r] = make_float4(fmaxf(v.x, 0.f), fmaxf(v.y, 0.f), fmaxf(v.z, 0.f), fmaxf(v.w, 0.f));
    }
#pragma unroll
    for (int r = 0; r < 4; r++) {
        int idx = tid + r * 256, kk = idx >> 5, n4 = idx & 31;
        pb[r] = (n4 < 16)
            ? *reinterpret_cast<const float4*>(W2 + (size_t)kk * H2 + n4 * 4)
            : *reinterpret_cast<const float4*>(W3 + (size_t)kk * H2 + (n4 - 16) * 4);
    }
    ull acc[4][4] = {};
    for (int c = 0; c < 4; c++) {
#pragma unroll
        for (int r = 0; r < 2; r++) {
            int idx = tid + r * 256, m = idx >> 3, k4 = idx & 7;
            *reinterpret_cast<float4*>(As + m * 36 + k4 * 4) = pa[r];
        }
#pragma unroll
        for (int r = 0; r < 4; r++) {
            int idx = tid + r * 256, kk = idx >> 5, n4 = idx & 31;
            *reinterpret_cast<float4*>(Bs + kk * 132 + n4 * 4) = pb[r];
        }
        __syncthreads();
        if (c < 3) {
            int kc = (c + 1) * 32;
#pragma unroll
            for (int r = 0; r < 2; r++) {
                int idx = tid + r * 256, m = idx >> 3, k4 = idx & 7;
                float4 v = *reinterpret_cast<const float4*>(g_h1 + (size_t)(mb + m) * H1 + kc + k4 * 4);
                pa[r] = make_float4(fmaxf(v.x, 0.f), fmaxf(v.y, 0.f), fmaxf(v.z, 0.f), fmaxf(v.w, 0.f));
            }
#pragma unroll
            for (int r = 0; r < 4; r++) {
                int idx = tid + r * 256, kk = idx >> 5, n4 = idx & 31;
                pb[r] = (n4 < 16)
                    ? *reinterpret_cast<const float4*>(W2 + (size_t)(kc + kk) * H2 + n4 * 4)
                    : *reinterpret_cast<const float4*>(W3 + (size_t)(kc + kk) * H2 + (n4 - 16) * 4);
            }
        }
        mma32<4>(As, Bs, ty, tx, acc);
        __syncthreads();
    }
#pragma unroll
    for (int i = 0; i < 4; i++) {
        int row = mb + ty * 4 + i;
        float cv[8];
#pragma unroll
        for (int jp = 0; jp < 4; jp++)
            asm("mov.b64 {%0, %1}, %2;" : "=f"(cv[jp*2]), "=f"(cv[jp*2+1]) : "l"(acc[i][jp]));
        float4* p = reinterpret_cast<float4*>(g_hw23 + (size_t)row * H1 + tx * 8);
        p[0] = make_float4(cv[0], cv[1], cv[2], cv[3]);
        p[1] = make_float4(cv[4], cv[5], cv[6], cv[7]);
    }
}

// ---------------- CSR aggregation: one warp per node ----------------
__global__ __launch_bounds__(256) void k_agg(int layer,
                                             const float* __restrict__ b1_,
                                             const float* __restrict__ b2_,
                                             const float* __restrict__ b3_) {
    int w = threadIdx.x >> 5, l = threadIdx.x & 31;
    int n = blockIdx.x * 8 + w;
    const float4* in = (layer == 1) ? (const float4*)g_hw1 : (const float4*)g_hw23;
    float4*      out = (layer == 1) ? (float4*)g_h1 : (float4*)g_mls;
    const float* bLo = (layer == 1) ? b1_ : b2_;
    const float* bHi = (layer == 1) ? b1_ + 64 : b3_;
    const float* bp = (l < 16) ? bLo + l * 4 : bHi + (l - 16) * 4;
    float4 bv = *reinterpret_cast<const float4*>(bp);
    float d = g_dis[n], d2 = d * d;
    float4 h = in[(size_t)n * 32 + l];
    float4 acc = make_float4(bv.x + d2 * h.x, bv.y + d2 * h.y,
                             bv.z + d2 * h.z, bv.w + d2 * h.w);
    int s = g_off[n], cnt = g_cnt[n];
    for (int base = 0; base < cnt; base += 32) {
        int j = base + l;
        int   rr = 0; float ww = 0.f;
        if (j < cnt) { rr = g_crow[s + j]; ww = g_cw[s + j]; }
        int m = cnt - base; if (m > 32) m = 32;
        for (int t = 0; t < m; t++) {
            float wv = __shfl_sync(FULLM, ww, t);
            int   rv = __shfl_sync(FULLM, rr, t);
            float4 vv = in[(size_t)rv * 32 + l];
            acc.x += wv * vv.x; acc.y += wv * vv.y;
            acc.z += wv * vv.z; acc.w += wv * vv.w;
        }
    }
    out[(size_t)n * 32 + l] = acc;
}

// ---------------- reparameterization ----------------
__global__ void k_z(const float* __restrict__ noise) {
    int idx = blockIdx.x * 256 + threadIdx.x;
    if (idx >= N_PAD * H2) return;
    int i = idx >> 6, f = idx & 63;
    float v = 0.f;
    if (i < N_NODES) {
        float mean = g_mls[i * H1 + f];
        float ls   = g_mls[i * H1 + 64 + f];
        v = mean + noise[idx] * expf(ls);
    }
    g_z[idx] = v;
}

// ---------------- decoder: out = sigmoid(z @ z^T), symmetric ----------------
__global__ __launch_bounds__(256) void k_decoder(float* __restrict__ out) {
    int bj = blockIdx.x, bi = blockIdx.y;
    if (bj < bi) return;
    __shared__ __align__(16) float As[128 * 36];
    __shared__ __align__(16) float Bs[32 * 132];
    int tid = threadIdx.x, tx = tid & 15, ty = tid >> 4;
    int rb = bi * 128, cb = bj * 128;
    float4 pa[4], pb[4];
#pragma unroll
    for (int r = 0; r < 4; r++) {                       // prefetch chunk 0
        int idx = tid + r * 256, m = idx >> 3, k4 = idx & 7;
        pa[r] = *reinterpret_cast<const float4*>(g_z + (size_t)(rb + m) * H2 + k4 * 4);
        pb[r] = *reinterpret_cast<const float4*>(g_z + (size_t)(cb + m) * H2 + k4 * 4);
    }
    ull acc[8][4] = {};
    for (int c = 0; c < 2; c++) {
#pragma unroll
        for (int r = 0; r < 4; r++) {
            int idx = tid + r * 256, m = idx >> 3, k4 = idx & 7;
            *reinterpret_cast<float4*>(As + m * 36 + k4 * 4) = pa[r];
            Bs[(k4 * 4 + 0) * 132 + m] = pb[r].x;       // transpose scatter
            Bs[(k4 * 4 + 1) * 132 + m] = pb[r].y;
            Bs[(k4 * 4 + 2) * 132 + m] = pb[r].z;
            Bs[(k4 * 4 + 3) * 132 + m] = pb[r].w;
        }
        __syncthreads();
        if (c == 0) {
#pragma unroll
            for (int r = 0; r < 4; r++) {
                int idx = tid + r * 256, m = idx >> 3, k4 = idx & 7;
                pa[r] = *reinterpret_cast<const float4*>(g_z + (size_t)(rb + m) * H2 + 32 + k4 * 4);
                pb[r] = *reinterpret_cast<const float4*>(g_z + (size_t)(cb + m) * H2 + 32 + k4 * 4);
            }
        }
        mma32<8>(As, Bs, ty, tx, acc);
        __syncthreads();
    }
    float cv[8][8];
#pragma unroll
    for (int i = 0; i < 8; i++)
#pragma unroll
        for (int jp = 0; jp < 4; jp++)
            asm("mov.b64 {%0, %1}, %2;" : "=f"(cv[i][jp*2]), "=f"(cv[i][jp*2+1]) : "l"(acc[i][jp]));
#pragma unroll
    for (int i = 0; i < 8; i++)
#pragma unroll
        for (int j = 0; j < 8; j++) {                   // sigmoid
            float e;
            asm("ex2.approx.f32 %0, %1;" : "=f"(e) : "f"(cv[i][j] * -1.4426950408889634f));
            asm("rcp.approx.f32 %0, %1;" : "=f"(cv[i][j]) : "f"(1.0f + e));
        }
    bool fullC = (cb + 128 <= N_NODES);
#pragma unroll
    for (int i = 0; i < 8; i++) {
        int row = rb + ty * 8 + i;
        if (row < N_NODES) {
            float* p = out + (size_t)row * N_NODES + cb + tx * 8;
            if (fullC) {
                *reinterpret_cast<float4*>(p)     = make_float4(cv[i][0], cv[i][1], cv[i][2], cv[i][3]);
                *reinterpret_cast<float4*>(p + 4) = make_float4(cv[i][4], cv[i][5], cv[i][6], cv[i][7]);
            } else {
                int c0 = cb + tx * 8;
#pragma unroll
                for (int j = 0; j < 8; j++) if (c0 + j < N_NODES) p[j] = cv[i][j];
            }
        }
    }
    if (bi != bj) {
        bool fullR = (rb + 128 <= N_NODES);
#pragma unroll
        for (int j = 0; j < 8; j++) {
            int row = cb + tx * 8 + j;
            if (row < N_NODES) {
                float* p = out + (size_t)row * N_NODES + rb + ty * 8;
                if (fullR) {
                    *reinterpret_cast<float4*>(p)     = make_float4(cv[0][j], cv[1][j], cv[2][j], cv[3][j]);
                    *reinterpret_cast<float4*>(p + 4) = make_float4(cv[4][j], cv[5][j], cv[6][j], cv[7][j]);
                } else {
                    int c0 = rb + ty * 8;
#pragma unroll
                    for (int ii = 0; ii < 8; ii++) if (c0 + ii < N_NODES) p[ii] = cv[ii][j];
                }
            }
        }
    }
}

// ---------------- launch ----------------
extern "C" void kernel_launch(void* const* d_in, const int* in_sizes, int n_in,
                              void* d_out, int out_size) {
    const float* x     = (const float*)d_in[0];
    const int*   ei    = (const int*)  d_in[1];
    const float* ew    = (const float*)d_in[2];
    const float* noise = (const float*)d_in[3];
    const float* W1    = (const float*)d_in[4];
    const float* b1    = (const float*)d_in[5];
    const float* W2    = (const float*)d_in[6];
    const float* b2    = (const float*)d_in[7];
    const float* W3    = (const float*)d_in[8];
    const float* b3    = (const float*)d_in[9];
    float* out = (float*)d_out;

    k_prep     <<<40, 256>>>();
    k_deg_edges<<<625, 256>>>(ei, ew);
    k_dis      <<<40, 256>>>();
    k_bsum     <<<40, 256>>>();
    k_scanb    <<<1, 64>>>();
    k_scan     <<<40, 256>>>();
    k_scatter  <<<625, 256>>>(ei, ew);

    k_gemm1    <<<157, 256>>>(x, W1);
    k_agg      <<<1250, 256>>>(1, b1, b2, b3);
    k_gemm23   <<<157, 256>>>(W2, W3);
    k_agg      <<<1250, 256>>>(2, b1, b2, b3);
    k_z        <<<(N_PAD * H2) / 256, 256>>>(noise);

    dim3 g(NT, NT);
    k_decoder  <<<g, 256>>>(out);
}

// round 4
// speedup vs baseline: 1.5723x; 1.5047x over previous
#include <cuda_runtime.h>
#include <cuda_bf16.h>
#include <math.h>
#include <stdint.h>

typedef unsigned long long ull;

#define N_NODES 10000
#define N_PAD   10112          // 79 * 128
#define E_EDGES 160000
#define D_IN    256
#define H1      128
#define H2      64
#define NT      79
#define FULLM   0xFFFFFFFFu

// ---------------- scratch (device globals) ----------------
__device__ float g_dis [N_NODES];
__device__ int   g_cnt [N_NODES];
__device__ int   g_off [N_NODES];
__device__ int   g_cur [N_NODES];
__device__ int   g_crow[E_EDGES];
__device__ float g_cw  [E_EDGES];
__device__ float g_hw1 [N_PAD * H1];
__device__ float g_h1  [N_PAD * H1];
__device__ float g_hw23[N_PAD * H1];
__device__ float g_mls [N_PAD * H1];
__device__ __align__(16) __nv_bfloat16 g_zhi[N_PAD * H2];
__device__ __align__(16) __nv_bfloat16 g_zlo[N_PAD * H2];

// ---------------- degree / CSR build ----------------
__global__ void k_prep() {
    int i = blockIdx.x * 256 + threadIdx.x;
    if (i < N_NODES) { g_dis[i] = 1.0f; g_cnt[i] = 0; }
}
__global__ void k_deg_edges(const int* __restrict__ ei, const float* __restrict__ ew) {
    int e = blockIdx.x * 256 + threadIdx.x;
    if (e < E_EDGES) {
        int c = ei[E_EDGES + e];
        atomicAdd(&g_dis[c], ew[e]);
        atomicAdd(&g_cnt[c], 1);
    }
}
// fused: exclusive scan of g_cnt -> g_off/g_cur, and g_dis = rsqrt(g_dis)
__global__ void k_scan_dis() {
    __shared__ int s[1024];
    int t = threadIdx.x;
    int base = t * 10;
    int pre[10]; int sum = 0;
#pragma unroll
    for (int i = 0; i < 10; i++) {
        int idx = base + i;
        int v = (idx < N_NODES) ? g_cnt[idx] : 0;
        pre[i] = sum; sum += v;
    }
    s[t] = sum; __syncthreads();
    for (int d = 1; d < 1024; d <<= 1) {
        int x = (t >= d) ? s[t - d] : 0;
        __syncthreads();
        s[t] += x;
        __syncthreads();
    }
    int excl = s[t] - sum;
#pragma unroll
    for (int i = 0; i < 10; i++) {
        int idx = base + i;
        if (idx < N_NODES) {
            int off = excl + pre[i];
            g_off[idx] = off; g_cur[idx] = off;
            g_dis[idx] = rsqrtf(g_dis[idx]);
        }
    }
}
__global__ void k_scatter(const int* __restrict__ ei, const float* __restrict__ ew) {
    int e = blockIdx.x * 256 + threadIdx.x;
    if (e < E_EDGES) {
        int r = ei[e], c = ei[E_EDGES + e];
        int p = atomicAdd(&g_cur[c], 1);
        g_crow[p] = r;
        g_cw[p]   = g_dis[r] * ew[e] * g_dis[c];
    }
}

// ---------------- f32x2 inner product over a 32-K chunk ----------------
template<int TM>
__device__ __forceinline__ void mma32(const float* __restrict__ As,
                                      const float* __restrict__ Bs,
                                      int ty, int tx, ull (&acc)[TM][4]) {
#pragma unroll
    for (int k = 0; k < 32; k++) {
        ulonglong2 p0 = *reinterpret_cast<const ulonglong2*>(Bs + k * 132 + tx * 8);
        ulonglong2 p1 = *reinterpret_cast<const ulonglong2*>(Bs + k * 132 + tx * 8 + 4);
        ull b[4] = {p0.x, p0.y, p1.x, p1.y};
#pragma unroll
        for (int i = 0; i < TM; i++) {
            float a = As[(ty * TM + i) * 36 + k];
            ull ad;
            asm("mov.b64 %0, {%1, %1};" : "=l"(ad) : "f"(a));
#pragma unroll
            for (int jp = 0; jp < 4; jp++)
                asm("fma.rn.f32x2 %0, %1, %2, %0;" : "+l"(acc[i][jp]) : "l"(ad), "l"(b[jp]));
        }
    }
}

// ---------------- GEMM1: g_hw1 = x @ W1  (32-row tiles, grid 313) ----------------
__global__ __launch_bounds__(256) void k_gemm1(const float* __restrict__ x,
                                               const float* __restrict__ W1) {
    __shared__ __align__(16) float As[32 * 36];
    __shared__ __align__(16) float Bs[32 * 132];
    int tid = threadIdx.x, tx = tid & 15, ty = tid >> 4;
    int mb = blockIdx.x * 32;
    float4 pa, pb[4];
    {
        int m = tid >> 3, k4 = tid & 7;
        pa = make_float4(0.f, 0.f, 0.f, 0.f);
        if (mb + m < N_NODES)
            pa = *reinterpret_cast<const float4*>(x + (size_t)(mb + m) * D_IN + k4 * 4);
    }
#pragma unroll
    for (int r = 0; r < 4; r++) {
        int idx = tid + r * 256, kk = idx >> 5, n4 = idx & 31;
        pb[r] = *reinterpret_cast<const float4*>(W1 + (size_t)kk * H1 + n4 * 4);
    }
    ull acc[2][4] = {};
    for (int c = 0; c < 8; c++) {
        {
            int m = tid >> 3, k4 = tid & 7;
            *reinterpret_cast<float4*>(As + m * 36 + k4 * 4) = pa;
        }
#pragma unroll
        for (int r = 0; r < 4; r++) {
            int idx = tid + r * 256, kk = idx >> 5, n4 = idx & 31;
            *reinterpret_cast<float4*>(Bs + kk * 132 + n4 * 4) = pb[r];
        }
        __syncthreads();
        if (c < 7) {
            int kc = (c + 1) * 32;
            int m = tid >> 3, k4 = tid & 7;
            pa = make_float4(0.f, 0.f, 0.f, 0.f);
            if (mb + m < N_NODES)
                pa = *reinterpret_cast<const float4*>(x + (size_t)(mb + m) * D_IN + kc + k4 * 4);
#pragma unroll
            for (int r = 0; r < 4; r++) {
                int idx = tid + r * 256, kk = idx >> 5, n4 = idx & 31;
                pb[r] = *reinterpret_cast<const float4*>(W1 + (size_t)(kc + kk) * H1 + n4 * 4);
            }
        }
        mma32<2>(As, Bs, ty, tx, acc);
        __syncthreads();
    }
#pragma unroll
    for (int i = 0; i < 2; i++) {
        int row = mb + ty * 2 + i;
        float cv[8];
#pragma unroll
        for (int jp = 0; jp < 4; jp++)
            asm("mov.b64 {%0, %1}, %2;" : "=f"(cv[jp*2]), "=f"(cv[jp*2+1]) : "l"(acc[i][jp]));
        float4* p = reinterpret_cast<float4*>(g_hw1 + (size_t)row * H1 + tx * 8);
        p[0] = make_float4(cv[0], cv[1], cv[2], cv[3]);
        p[1] = make_float4(cv[4], cv[5], cv[6], cv[7]);
    }
}

// ---------------- GEMM23: g_hw23 = relu(g_h1) @ [W2|W3]  (32-row tiles) ----------------
__global__ __launch_bounds__(256) void k_gemm23(const float* __restrict__ W2,
                                                const float* __restrict__ W3) {
    __shared__ __align__(16) float As[32 * 36];
    __shared__ __align__(16) float Bs[32 * 132];
    int tid = threadIdx.x, tx = tid & 15, ty = tid >> 4;
    int mb = blockIdx.x * 32;
    float4 pa, pb[4];
    {
        int m = tid >> 3, k4 = tid & 7;
        float4 v = *reinterpret_cast<const float4*>(g_h1 + (size_t)(mb + m) * H1 + k4 * 4);
        pa = make_float4(fmaxf(v.x, 0.f), fmaxf(v.y, 0.f), fmaxf(v.z, 0.f), fmaxf(v.w, 0.f));
    }
#pragma unroll
    for (int r = 0; r < 4; r++) {
        int idx = tid + r * 256, kk = idx >> 5, n4 = idx & 31;
        pb[r] = (n4 < 16)
            ? *reinterpret_cast<const float4*>(W2 + (size_t)kk * H2 + n4 * 4)
            : *reinterpret_cast<const float4*>(W3 + (size_t)kk * H2 + (n4 - 16) * 4);
    }
    ull acc[2][4] = {};
    for (int c = 0; c < 4; c++) {
        {
            int m = tid >> 3, k4 = tid & 7;
            *reinterpret_cast<float4*>(As + m * 36 + k4 * 4) = pa;
        }
#pragma unroll
        for (int r = 0; r < 4; r++) {
            int idx = tid + r * 256, kk = idx >> 5, n4 = idx & 31;
            *reinterpret_cast<float4*>(Bs + kk * 132 + n4 * 4) = pb[r];
        }
        __syncthreads();
        if (c < 3) {
            int kc = (c + 1) * 32;
            int m = tid >> 3, k4 = tid & 7;
            float4 v = *reinterpret_cast<const float4*>(g_h1 + (size_t)(mb + m) * H1 + kc + k4 * 4);
            pa = make_float4(fmaxf(v.x, 0.f), fmaxf(v.y, 0.f), fmaxf(v.z, 0.f), fmaxf(v.w, 0.f));
#pragma unroll
            for (int r = 0; r < 4; r++) {
                int idx = tid + r * 256, kk = idx >> 5, n4 = idx & 31;
                pb[r] = (n4 < 16)
                    ? *reinterpret_cast<const float4*>(W2 + (size_t)(kc + kk) * H2 + n4 * 4)
                    : *reinterpret_cast<const float4*>(W3 + (size_t)(kc + kk) * H2 + (n4 - 16) * 4);
            }
        }
        mma32<2>(As, Bs, ty, tx, acc);
        __syncthreads();
    }
#pragma unroll
    for (int i = 0; i < 2; i++) {
        int row = mb + ty * 2 + i;
        float cv[8];
#pragma unroll
        for (int jp = 0; jp < 4; jp++)
            asm("mov.b64 {%0, %1}, %2;" : "=f"(cv[jp*2]), "=f"(cv[jp*2+1]) : "l"(acc[i][jp]));
        float4* p = reinterpret_cast<float4*>(g_hw23 + (size_t)row * H1 + tx * 8);
        p[0] = make_float4(cv[0], cv[1], cv[2], cv[3]);
        p[1] = make_float4(cv[4], cv[5], cv[6], cv[7]);
    }
}

// ---------------- CSR aggregation: one warp per node ----------------
__global__ __launch_bounds__(256) void k_agg(int layer,
                                             const float* __restrict__ b1_,
                                             const float* __restrict__ b2_,
                                             const float* __restrict__ b3_) {
    int w = threadIdx.x >> 5, l = threadIdx.x & 31;
    int n = blockIdx.x * 8 + w;
    const float4* in = (layer == 1) ? (const float4*)g_hw1 : (const float4*)g_hw23;
    float4*      out = (layer == 1) ? (float4*)g_h1 : (float4*)g_mls;
    const float* bLo = (layer == 1) ? b1_ : b2_;
    const float* bHi = (layer == 1) ? b1_ + 64 : b3_;
    const float* bp = (l < 16) ? bLo + l * 4 : bHi + (l - 16) * 4;
    float4 bv = *reinterpret_cast<const float4*>(bp);
    float d = g_dis[n], d2 = d * d;
    float4 h = in[(size_t)n * 32 + l];
    float4 acc = make_float4(bv.x + d2 * h.x, bv.y + d2 * h.y,
                             bv.z + d2 * h.z, bv.w + d2 * h.w);
    int s = g_off[n], cnt = g_cnt[n];
    for (int base = 0; base < cnt; base += 32) {
        int j = base + l;
        int   rr = 0; float ww = 0.f;
        if (j < cnt) { rr = g_crow[s + j]; ww = g_cw[s + j]; }
        int m = cnt - base; if (m > 32) m = 32;
        for (int t = 0; t < m; t++) {
            float wv = __shfl_sync(FULLM, ww, t);
            int   rv = __shfl_sync(FULLM, rr, t);
            float4 vv = in[(size_t)rv * 32 + l];
            acc.x += wv * vv.x; acc.y += wv * vv.y;
            acc.z += wv * vv.z; acc.w += wv * vv.w;
        }
    }
    out[(size_t)n * 32 + l] = acc;
}

// ---------------- reparameterization + bf16 hi/lo split ----------------
__global__ void k_z(const float* __restrict__ noise) {
    int idx = blockIdx.x * 256 + threadIdx.x;
    if (idx >= N_PAD * H2) return;
    int i = idx >> 6, f = idx & 63;
    float v = 0.f;
    if (i < N_NODES) {
        float mean = g_mls[i * H1 + f];
        float ls   = g_mls[i * H1 + 64 + f];
        v = mean + noise[idx] * expf(ls);
    }
    __nv_bfloat16 hi = __float2bfloat16(v);
    g_zhi[idx] = hi;
    g_zlo[idx] = __float2bfloat16(v - __bfloat162float(hi));
}

// ---------------- mma.sync decoder ----------------
__device__ __forceinline__ uint32_t s2u(const void* p) {
    uint32_t a;
    asm("{ .reg .u64 t; cvta.to.shared.u64 t, %1; cvt.u32.u64 %0, t; }" : "=r"(a) : "l"(p));
    return a;
}
__device__ __forceinline__ void ldsm4(uint32_t* r, uint32_t addr) {
    asm volatile("ldmatrix.sync.aligned.m8n8.x4.shared.b16 {%0,%1,%2,%3}, [%4];"
        : "=r"(r[0]), "=r"(r[1]), "=r"(r[2]), "=r"(r[3]) : "r"(addr));
}
__device__ __forceinline__ void ldsm2(uint32_t* r, uint32_t addr) {
    asm volatile("ldmatrix.sync.aligned.m8n8.x2.shared.b16 {%0,%1}, [%2];"
        : "=r"(r[0]), "=r"(r[1]) : "r"(addr));
}
__device__ __forceinline__ void hmma(float* d, const uint32_t* a, const uint32_t* b) {
    asm volatile("mma.sync.aligned.m16n8k16.row.col.f32.bf16.bf16.f32 "
        "{%0,%1,%2,%3}, {%4,%5,%6,%7}, {%8,%9}, {%0,%1,%2,%3};"
        : "+f"(d[0]), "+f"(d[1]), "+f"(d[2]), "+f"(d[3])
        : "r"(a[0]), "r"(a[1]), "r"(a[2]), "r"(a[3]), "r"(b[0]), "r"(b[1]));
}
__device__ __forceinline__ float sigf(float x) {
    float e, r;
    asm("ex2.approx.f32 %0, %1;" : "=f"(e) : "f"(x * -1.4426950408889634f));
    asm("rcp.approx.f32 %0, %1;" : "=f"(r) : "f"(1.0f + e));
    return r;
}

#define LDB 72                    // halves per row (64 + 8 pad, conflict-free ldmatrix)
#define TILE_B (128 * LDB * 2)    // 18432 bytes per tile
#define DEC_SMEM (4 * TILE_B)     // Ahi, Alo, Bhi, Blo

__global__ __launch_bounds__(256, 2) void k_decoder(float* __restrict__ out) {
    int bj = blockIdx.x, bi = blockIdx.y;
    if (bj < bi) return;
    extern __shared__ char sm[];
    uint32_t sb = s2u(sm);
    int tid = threadIdx.x, lane = tid & 31, wid = tid >> 5;
    int wm = wid >> 2, wn = wid & 3;                   // warps: 2(M) x 4(N)
    int rb = bi * 128, cb = bj * 128;

    // load 4 tiles: Ahi(0) Alo(1) Bhi(2) Blo(3); 16 uint4 per thread
    const uint4* zhi = reinterpret_cast<const uint4*>(g_zhi);
    const uint4* zlo = reinterpret_cast<const uint4*>(g_zlo);
#pragma unroll
    for (int i = 0; i < 16; i++) {
        int idx = tid + i * 256;
        int tile = idx >> 10, rem = idx & 1023;
        int r = rem >> 3, c = rem & 7;
        int grow = ((tile & 2) ? cb : rb) + r;
        uint4 v = (tile & 1) ? zlo[(size_t)grow * 8 + c] : zhi[(size_t)grow * 8 + c];
        *reinterpret_cast<uint4*>(sm + tile * TILE_B + r * (LDB * 2) + c * 16) = v;
    }
    __syncthreads();

    uint32_t aH = sb, aL = sb + TILE_B, bH = sb + 2 * TILE_B, bL = sb + 3 * TILE_B;
    int lrow = lane & 15, ksel = lane >> 4;            // ldmatrix.x4 (A)
    int brow = lane & 7,  bsel = (lane >> 3) & 1;      // ldmatrix.x2 (B)

    float acc[4][4][4] = {};
#pragma unroll
    for (int k = 0; k < 4; k++) {
        uint32_t bh[4][2], bl[4][2], af[4][4];
#pragma unroll
        for (int nt = 0; nt < 4; nt++) {
            uint32_t boff = ((wn * 32 + nt * 8 + brow) * LDB + k * 16 + bsel * 8) * 2;
            ldsm2(bh[nt], bH + boff);
            ldsm2(bl[nt], bL + boff);
        }
#pragma unroll
        for (int mt = 0; mt < 4; mt++) {
            uint32_t aoff = ((wm * 64 + mt * 16 + lrow) * LDB + k * 16 + ksel * 8) * 2;
            ldsm4(af[mt], aH + aoff);
        }
#pragma unroll
        for (int mt = 0; mt < 4; mt++)
#pragma unroll
            for (int nt = 0; nt < 4; nt++) hmma(acc[mt][nt], af[mt], bh[nt]);
#pragma unroll
        for (int mt = 0; mt < 4; mt++)
#pragma unroll
            for (int nt = 0; nt < 4; nt++) hmma(acc[mt][nt], af[mt], bl[nt]);
#pragma unroll
        for (int mt = 0; mt < 4; mt++) {
            uint32_t aoff = ((wm * 64 + mt * 16 + lrow) * LDB + k * 16 + ksel * 8) * 2;
            ldsm4(af[mt], aL + aoff);
        }
#pragma unroll
        for (int mt = 0; mt < 4; mt++)
#pragma unroll
            for (int nt = 0; nt < 4; nt++) hmma(acc[mt][nt], af[mt], bh[nt]);
    }

    // epilogue: sigmoid + direct (float2 coalesced) + mirrored stores
    int tr = lane >> 2, tc = (lane & 3) * 2;
    bool diag = (bi == bj);
#pragma unroll
    for (int mt = 0; mt < 4; mt++) {
        int r0 = rb + wm * 64 + mt * 16 + tr;
        int r1 = r0 + 8;
#pragma unroll
        for (int nt = 0; nt < 4; nt++) {
            int cc = cb + wn * 32 + nt * 8 + tc;
            float s0 = sigf(acc[mt][nt][0]);
            float s1 = sigf(acc[mt][nt][1]);
            float s2 = sigf(acc[mt][nt][2]);
            float s3 = sigf(acc[mt][nt][3]);
            if (r0 < N_NODES) {
                if (cc + 1 < N_NODES)
                    *reinterpret_cast<float2*>(out + (size_t)r0 * N_NODES + cc) = make_float2(s0, s1);
                else if (cc < N_NODES)
                    out[(size_t)r0 * N_NODES + cc] = s0;
            }
            if (r1 < N_NODES) {
                if (cc + 1 < N_NODES)
                    *reinterpret_cast<float2*>(out + (size_t)r1 * N_NODES + cc) = make_float2(s2, s3);
                else if (cc < N_NODES)
                    out[(size_t)r1 * N_NODES + cc] = s2;
            }
            if (!diag) {
                if (cc < N_NODES) {
                    if (r0 < N_NODES) out[(size_t)cc * N_NODES + r0] = s0;
                    if (r1 < N_NODES) out[(size_t)cc * N_NODES + r1] = s2;
                }
                if (cc + 1 < N_NODES) {
                    if (r0 < N_NODES) out[(size_t)(cc + 1) * N_NODES + r0] = s1;
                    if (r1 < N_NODES) out[(size_t)(cc + 1) * N_NODES + r1] = s3;
                }
            }
        }
    }
}

// ---------------- launch ----------------
extern "C" void kernel_launch(void* const* d_in, const int* in_sizes, int n_in,
                              void* d_out, int out_size) {
    const float* x     = (const float*)d_in[0];
    const int*   ei    = (const int*)  d_in[1];
    const float* ew    = (const float*)d_in[2];
    const float* noise = (const float*)d_in[3];
    const float* W1    = (const float*)d_in[4];
    const float* b1    = (const float*)d_in[5];
    const float* W2    = (const float*)d_in[6];
    const float* b2    = (const float*)d_in[7];
    const float* W3    = (const float*)d_in[8];
    const float* b3    = (const float*)d_in[9];
    float* out = (float*)d_out;

    static int smem_set = 0;
    if (!smem_set) {
        cudaFuncSetAttribute(k_decoder, cudaFuncAttributeMaxDynamicSharedMemorySize, DEC_SMEM);
        smem_set = 1;
    }

    k_gemm1    <<<313, 256>>>(x, W1);                  // 0
    k_prep     <<<40, 256>>>();                        // 1
    k_deg_edges<<<625, 256>>>(ei, ew);                 // 2
    k_scan_dis <<<1, 1024>>>();                        // 3
    k_scatter  <<<625, 256>>>(ei, ew);                 // 4
    k_agg      <<<1250, 256>>>(1, b1, b2, b3);         // 5  <- profiled (-s 5)
    k_gemm23   <<<313, 256>>>(W2, W3);                 // 6
    k_agg      <<<1250, 256>>>(2, b1, b2, b3);         // 7
    k_z        <<<(N_PAD * H2) / 256, 256>>>(noise);   // 8
    dim3 g(NT, NT);
    k_decoder  <<<g, 256, DEC_SMEM>>>(out);            // 9
}

// round 5
// speedup vs baseline: 1.6691x; 1.0615x over previous
#include <cuda_runtime.h>
#include <cuda_bf16.h>
#include <math.h>
#include <stdint.h>

typedef unsigned long long ull;

#define N_NODES 10000
#define N_PAD   10112          // 79 * 128
#define E_EDGES 160000
#define D_IN    256
#define H1      128
#define H2      64
#define NT      79
#define FULLM   0xFFFFFFFFu

// ---------------- scratch (device globals) ----------------
__device__ float g_dis [N_NODES];
__device__ int   g_cnt [N_NODES];
__device__ int   g_off [N_NODES];
__device__ int   g_cur [N_NODES];
__device__ int   g_total;
__device__ int   g_crow[E_EDGES];
__device__ float g_cw  [E_EDGES];
__device__ float g_hw1 [N_PAD * H1];
__device__ float g_h1  [N_PAD * H1];
__device__ float g_hw23[N_PAD * H1];
__device__ float g_mls [N_PAD * H1];
__device__ __align__(16) __nv_bfloat16 g_zhi[N_PAD * H2];
__device__ __align__(16) __nv_bfloat16 g_zlo[N_PAD * H2];

// ---------------- degree / CSR build ----------------
__global__ void k_prep() {
    int i = blockIdx.x * 256 + threadIdx.x;
    if (i < N_NODES) { g_dis[i] = 1.0f; g_cnt[i] = 0; }
    if (i == 0) g_total = 0;
}
__global__ void k_deg_edges(const int* __restrict__ ei, const float* __restrict__ ew) {
    int e = blockIdx.x * 256 + threadIdx.x;
    if (e < E_EDGES) {
        int c = ei[E_EDGES + e];
        atomicAdd(&g_dis[c], ew[e]);
        atomicAdd(&g_cnt[c], 1);
    }
}
// parallel offset allocation: block-local scan + atomic base grab; also rsqrt(deg).
// Node ranges are disjoint & contiguous; global order is irrelevant for correctness.
__global__ void k_offsets() {
    __shared__ int s[256];
    __shared__ int sbase;
    int t = threadIdx.x;
    int i = blockIdx.x * 256 + t;
    int v = (i < N_NODES) ? g_cnt[i] : 0;
    s[t] = v; __syncthreads();
    for (int d = 1; d < 256; d <<= 1) {
        int x = (t >= d) ? s[t - d] : 0;
        __syncthreads();
        s[t] += x;
        __syncthreads();
    }
    if (t == 255) sbase = atomicAdd(&g_total, s[255]);
    __syncthreads();
    if (i < N_NODES) {
        int off = sbase + s[t] - v;
        g_off[i] = off; g_cur[i] = off;
        g_dis[i] = rsqrtf(g_dis[i]);
    }
}
__global__ void k_scatter(const int* __restrict__ ei, const float* __restrict__ ew) {
    int e = blockIdx.x * 256 + threadIdx.x;
    if (e < E_EDGES) {
        int r = ei[e], c = ei[E_EDGES + e];
        int p = atomicAdd(&g_cur[c], 1);
        g_crow[p] = r;
        g_cw[p]   = g_dis[r] * ew[e] * g_dis[c];
    }
}

// ---------------- f32x2 inner product over a 32-K chunk ----------------
template<int TM>
__device__ __forceinline__ void mma32(const float* __restrict__ As,
                                      const float* __restrict__ Bs,
                                      int ty, int tx, ull (&acc)[TM][4]) {
#pragma unroll
    for (int k = 0; k < 32; k++) {
        ulonglong2 p0 = *reinterpret_cast<const ulonglong2*>(Bs + k * 132 + tx * 8);
        ulonglong2 p1 = *reinterpret_cast<const ulonglong2*>(Bs + k * 132 + tx * 8 + 4);
        ull b[4] = {p0.x, p0.y, p1.x, p1.y};
#pragma unroll
        for (int i = 0; i < TM; i++) {
            float a = As[(ty * TM + i) * 36 + k];
            ull ad;
            asm("mov.b64 %0, {%1, %1};" : "=l"(ad) : "f"(a));
#pragma unroll
            for (int jp = 0; jp < 4; jp++)
                asm("fma.rn.f32x2 %0, %1, %2, %0;" : "+l"(acc[i][jp]) : "l"(ad), "l"(b[jp]));
        }
    }
}

// ---------------- GEMM1: g_hw1 = x @ W1  (32-row tiles, grid 313) ----------------
__global__ __launch_bounds__(256) void k_gemm1(const float* __restrict__ x,
                                               const float* __restrict__ W1) {
    __shared__ __align__(16) float As[32 * 36];
    __shared__ __align__(16) float Bs[32 * 132];
    int tid = threadIdx.x, tx = tid & 15, ty = tid >> 4;
    int mb = blockIdx.x * 32;
    float4 pa, pb[4];
    {
        int m = tid >> 3, k4 = tid & 7;
        pa = make_float4(0.f, 0.f, 0.f, 0.f);
        if (mb + m < N_NODES)
            pa = *reinterpret_cast<const float4*>(x + (size_t)(mb + m) * D_IN + k4 * 4);
    }
#pragma unroll
    for (int r = 0; r < 4; r++) {
        int idx = tid + r * 256, kk = idx >> 5, n4 = idx & 31;
        pb[r] = *reinterpret_cast<const float4*>(W1 + (size_t)kk * H1 + n4 * 4);
    }
    ull acc[2][4] = {};
    for (int c = 0; c < 8; c++) {
        {
            int m = tid >> 3, k4 = tid & 7;
            *reinterpret_cast<float4*>(As + m * 36 + k4 * 4) = pa;
        }
#pragma unroll
        for (int r = 0; r < 4; r++) {
            int idx = tid + r * 256, kk = idx >> 5, n4 = idx & 31;
            *reinterpret_cast<float4*>(Bs + kk * 132 + n4 * 4) = pb[r];
        }
        __syncthreads();
        if (c < 7) {
            int kc = (c + 1) * 32;
            int m = tid >> 3, k4 = tid & 7;
            pa = make_float4(0.f, 0.f, 0.f, 0.f);
            if (mb + m < N_NODES)
                pa = *reinterpret_cast<const float4*>(x + (size_t)(mb + m) * D_IN + kc + k4 * 4);
#pragma unroll
            for (int r = 0; r < 4; r++) {
                int idx = tid + r * 256, kk = idx >> 5, n4 = idx & 31;
                pb[r] = *reinterpret_cast<const float4*>(W1 + (size_t)(kc + kk) * H1 + n4 * 4);
            }
        }
        mma32<2>(As, Bs, ty, tx, acc);
        __syncthreads();
    }
#pragma unroll
    for (int i = 0; i < 2; i++) {
        int row = mb + ty * 2 + i;
        float cv[8];
#pragma unroll
        for (int jp = 0; jp < 4; jp++)
            asm("mov.b64 {%0, %1}, %2;" : "=f"(cv[jp*2]), "=f"(cv[jp*2+1]) : "l"(acc[i][jp]));
        float4* p = reinterpret_cast<float4*>(g_hw1 + (size_t)row * H1 + tx * 8);
        p[0] = make_float4(cv[0], cv[1], cv[2], cv[3]);
        p[1] = make_float4(cv[4], cv[5], cv[6], cv[7]);
    }
}

// ---------------- GEMM23: g_hw23 = relu(g_h1) @ [W2|W3]  (32-row tiles) ----------------
__global__ __launch_bounds__(256) void k_gemm23(const float* __restrict__ W2,
                                                const float* __restrict__ W3) {
    __shared__ __align__(16) float As[32 * 36];
    __shared__ __align__(16) float Bs[32 * 132];
    int tid = threadIdx.x, tx = tid & 15, ty = tid >> 4;
    int mb = blockIdx.x * 32;
    float4 pa, pb[4];
    {
        int m = tid >> 3, k4 = tid & 7;
        float4 v = *reinterpret_cast<const float4*>(g_h1 + (size_t)(mb + m) * H1 + k4 * 4);
        pa = make_float4(fmaxf(v.x, 0.f), fmaxf(v.y, 0.f), fmaxf(v.z, 0.f), fmaxf(v.w, 0.f));
    }
#pragma unroll
    for (int r = 0; r < 4; r++) {
        int idx = tid + r * 256, kk = idx >> 5, n4 = idx & 31;
        pb[r] = (n4 < 16)
            ? *reinterpret_cast<const float4*>(W2 + (size_t)kk * H2 + n4 * 4)
            : *reinterpret_cast<const float4*>(W3 + (size_t)kk * H2 + (n4 - 16) * 4);
    }
    ull acc[2][4] = {};
    for (int c = 0; c < 4; c++) {
        {
            int m = tid >> 3, k4 = tid & 7;
            *reinterpret_cast<float4*>(As + m * 36 + k4 * 4) = pa;
        }
#pragma unroll
        for (int r = 0; r < 4; r++) {
            int idx = tid + r * 256, kk = idx >> 5, n4 = idx & 31;
            *reinterpret_cast<float4*>(Bs + kk * 132 + n4 * 4) = pb[r];
        }
        __syncthreads();
        if (c < 3) {
            int kc = (c + 1) * 32;
            int m = tid >> 3, k4 = tid & 7;
            float4 v = *reinterpret_cast<const float4*>(g_h1 + (size_t)(mb + m) * H1 + kc + k4 * 4);
            pa = make_float4(fmaxf(v.x, 0.f), fmaxf(v.y, 0.f), fmaxf(v.z, 0.f), fmaxf(v.w, 0.f));
#pragma unroll
            for (int r = 0; r < 4; r++) {
                int idx = tid + r * 256, kk = idx >> 5, n4 = idx & 31;
                pb[r] = (n4 < 16)
                    ? *reinterpret_cast<const float4*>(W2 + (size_t)(kc + kk) * H2 + n4 * 4)
                    : *reinterpret_cast<const float4*>(W3 + (size_t)(kc + kk) * H2 + (n4 - 16) * 4);
            }
        }
        mma32<2>(As, Bs, ty, tx, acc);
        __syncthreads();
    }
#pragma unroll
    for (int i = 0; i < 2; i++) {
        int row = mb + ty * 2 + i;
        float cv[8];
#pragma unroll
        for (int jp = 0; jp < 4; jp++)
            asm("mov.b64 {%0, %1}, %2;" : "=f"(cv[jp*2]), "=f"(cv[jp*2+1]) : "l"(acc[i][jp]));
        float4* p = reinterpret_cast<float4*>(g_hw23 + (size_t)row * H1 + tx * 8);
        p[0] = make_float4(cv[0], cv[1], cv[2], cv[3]);
        p[1] = make_float4(cv[4], cv[5], cv[6], cv[7]);
    }
}

// ---------------- CSR aggregation: one warp per node ----------------
__global__ __launch_bounds__(256) void k_agg(int layer,
                                             const float* __restrict__ b1_,
                                             const float* __restrict__ b2_,
                                             const float* __restrict__ b3_) {
    int w = threadIdx.x >> 5, l = threadIdx.x & 31;
    int n = blockIdx.x * 8 + w;
    const float4* in = (layer == 1) ? (const float4*)g_hw1 : (const float4*)g_hw23;
    float4*      out = (layer == 1) ? (float4*)g_h1 : (float4*)g_mls;
    const float* bLo = (layer == 1) ? b1_ : b2_;
    const float* bHi = (layer == 1) ? b1_ + 64 : b3_;
    const float* bp = (l < 16) ? bLo + l * 4 : bHi + (l - 16) * 4;
    float4 bv = *reinterpret_cast<const float4*>(bp);
    float d = g_dis[n], d2 = d * d;
    float4 h = in[(size_t)n * 32 + l];
    float4 acc = make_float4(bv.x + d2 * h.x, bv.y + d2 * h.y,
                             bv.z + d2 * h.z, bv.w + d2 * h.w);
    int s = g_off[n], cnt = g_cnt[n];
    for (int base = 0; base < cnt; base += 32) {
        int j = base + l;
        int   rr = 0; float ww = 0.f;
        if (j < cnt) { rr = g_crow[s + j]; ww = g_cw[s + j]; }
        int m = cnt - base; if (m > 32) m = 32;
        for (int t = 0; t < m; t++) {
            float wv = __shfl_sync(FULLM, ww, t);
            int   rv = __shfl_sync(FULLM, rr, t);
            float4 vv = in[(size_t)rv * 32 + l];
            acc.x += wv * vv.x; acc.y += wv * vv.y;
            acc.z += wv * vv.z; acc.w += wv * vv.w;
        }
    }
    out[(size_t)n * 32 + l] = acc;
}

// ---------------- reparameterization + bf16 hi/lo split ----------------
__global__ void k_z(const float* __restrict__ noise) {
    int idx = blockIdx.x * 256 + threadIdx.x;
    if (idx >= N_PAD * H2) return;
    int i = idx >> 6, f = idx & 63;
    float v = 0.f;
    if (i < N_NODES) {
        float mean = g_mls[i * H1 + f];
        float ls   = g_mls[i * H1 + 64 + f];
        v = mean + noise[idx] * expf(ls);
    }
    __nv_bfloat16 hi = __float2bfloat16(v);
    g_zhi[idx] = hi;
    g_zlo[idx] = __float2bfloat16(v - __bfloat162float(hi));
}

// ---------------- mma.sync decoder ----------------
__device__ __forceinline__ uint32_t s2u(const void* p) {
    uint32_t a;
    asm("{ .reg .u64 t; cvta.to.shared.u64 t, %1; cvt.u32.u64 %0, t; }" : "=r"(a) : "l"(p));
    return a;
}
__device__ __forceinline__ void ldsm4(uint32_t* r, uint32_t addr) {
    asm volatile("ldmatrix.sync.aligned.m8n8.x4.shared.b16 {%0,%1,%2,%3}, [%4];"
        : "=r"(r[0]), "=r"(r[1]), "=r"(r[2]), "=r"(r[3]) : "r"(addr));
}
__device__ __forceinline__ void ldsm2(uint32_t* r, uint32_t addr) {
    asm volatile("ldmatrix.sync.aligned.m8n8.x2.shared.b16 {%0,%1}, [%2];"
        : "=r"(r[0]), "=r"(r[1]) : "r"(addr));
}
__device__ __forceinline__ void hmma(float* d, const uint32_t* a, const uint32_t* b) {
    asm volatile("mma.sync.aligned.m16n8k16.row.col.f32.bf16.bf16.f32 "
        "{%0,%1,%2,%3}, {%4,%5,%6,%7}, {%8,%9}, {%0,%1,%2,%3};"
        : "+f"(d[0]), "+f"(d[1]), "+f"(d[2]), "+f"(d[3])
        : "r"(a[0]), "r"(a[1]), "r"(a[2]), "r"(a[3]), "r"(b[0]), "r"(b[1]));
}
__device__ __forceinline__ float sigf(float x) {
    float e, r;
    asm("ex2.approx.f32 %0, %1;" : "=f"(e) : "f"(x * -1.4426950408889634f));
    asm("rcp.approx.f32 %0, %1;" : "=f"(r) : "f"(1.0f + e));
    return r;
}

#define LDB 72                    // halves per row (64 + 8 pad, conflict-free ldmatrix)
#define TILE_B (128 * LDB * 2)    // 18432 bytes per tile
#define PT 132                    // staging pitch (floats): STS banks (8a+b), LDS.128 aligned
#define DEC_SMEM (4 * TILE_B)     // 73728 >= 128*PT*4 = 67584 staging

__global__ __launch_bounds__(256, 2) void k_decoder(float* __restrict__ out) {
    int bj = blockIdx.x, bi = blockIdx.y;
    if (bj < bi) return;
    extern __shared__ char sm[];
    uint32_t sb = s2u(sm);
    int tid = threadIdx.x, lane = tid & 31, wid = tid >> 5;
    int wm = wid >> 2, wn = wid & 3;                   // warps: 2(M) x 4(N)
    int rb = bi * 128, cb = bj * 128;

    // load 4 tiles: Ahi(0) Alo(1) Bhi(2) Blo(3); 16 uint4 per thread
    const uint4* zhi = reinterpret_cast<const uint4*>(g_zhi);
    const uint4* zlo = reinterpret_cast<const uint4*>(g_zlo);
#pragma unroll
    for (int i = 0; i < 16; i++) {
        int idx = tid + i * 256;
        int tile = idx >> 10, rem = idx & 1023;
        int r = rem >> 3, c = rem & 7;
        int grow = ((tile & 2) ? cb : rb) + r;
        uint4 v = (tile & 1) ? zlo[(size_t)grow * 8 + c] : zhi[(size_t)grow * 8 + c];
        *reinterpret_cast<uint4*>(sm + tile * TILE_B + r * (LDB * 2) + c * 16) = v;
    }
    __syncthreads();

    uint32_t aH = sb, aL = sb + TILE_B, bH = sb + 2 * TILE_B, bL = sb + 3 * TILE_B;
    int lrow = lane & 15, ksel = lane >> 4;            // ldmatrix.x4 (A)
    int brow = lane & 7,  bsel = (lane >> 3) & 1;      // ldmatrix.x2 (B)

    float acc[4][4][4] = {};
#pragma unroll
    for (int k = 0; k < 4; k++) {
        uint32_t bh[4][2], bl[4][2], af[4][4];
#pragma unroll
        for (int nt = 0; nt < 4; nt++) {
            uint32_t boff = ((wn * 32 + nt * 8 + brow) * LDB + k * 16 + bsel * 8) * 2;
            ldsm2(bh[nt], bH + boff);
            ldsm2(bl[nt], bL + boff);
        }
#pragma unroll
        for (int mt = 0; mt < 4; mt++) {
            uint32_t aoff = ((wm * 64 + mt * 16 + lrow) * LDB + k * 16 + ksel * 8) * 2;
            ldsm4(af[mt], aH + aoff);
        }
#pragma unroll
        for (int mt = 0; mt < 4; mt++)
#pragma unroll
            for (int nt = 0; nt < 4; nt++) hmma(acc[mt][nt], af[mt], bh[nt]);
#pragma unroll
        for (int mt = 0; mt < 4; mt++)
#pragma unroll
            for (int nt = 0; nt < 4; nt++) hmma(acc[mt][nt], af[mt], bl[nt]);
#pragma unroll
        for (int mt = 0; mt < 4; mt++) {
            uint32_t aoff = ((wm * 64 + mt * 16 + lrow) * LDB + k * 16 + ksel * 8) * 2;
            ldsm4(af[mt], aL + aoff);
        }
#pragma unroll
        for (int mt = 0; mt < 4; mt++)
#pragma unroll
            for (int nt = 0; nt < 4; nt++) hmma(acc[mt][nt], af[mt], bh[nt]);
    }

    // sigmoid in place
#pragma unroll
    for (int mt = 0; mt < 4; mt++)
#pragma unroll
        for (int nt = 0; nt < 4; nt++)
#pragma unroll
            for (int q = 0; q < 4; q++) acc[mt][nt][q] = sigf(acc[mt][nt][q]);

    // direct tile from regs (coalesced float2 per 8-lane row-group)
    int tr = lane >> 2, tc = (lane & 3) * 2;
    bool diag = (bi == bj);
#pragma unroll
    for (int mt = 0; mt < 4; mt++) {
        int r0 = rb + wm * 64 + mt * 16 + tr;
        int r1 = r0 + 8;
#pragma unroll
        for (int nt = 0; nt < 4; nt++) {
            int cc = cb + wn * 32 + nt * 8 + tc;
            if (r0 < N_NODES) {
                if (cc + 1 < N_NODES)
                    *reinterpret_cast<float2*>(out + (size_t)r0 * N_NODES + cc) =
                        make_float2(acc[mt][nt][0], acc[mt][nt][1]);
                else if (cc < N_NODES)
                    out[(size_t)r0 * N_NODES + cc] = acc[mt][nt][0];
            }
            if (r1 < N_NODES) {
                if (cc + 1 < N_NODES)
                    *reinterpret_cast<float2*>(out + (size_t)r1 * N_NODES + cc) =
                        make_float2(acc[mt][nt][2], acc[mt][nt][3]);
                else if (cc < N_NODES)
                    out[(size_t)r1 * N_NODES + cc] = acc[mt][nt][2];
            }
        }
    }

    // mirrored tile via smem transpose -> coalesced float4 row writes
    if (!diag) {
        __syncthreads();                                // ldmatrix consumers done
        float* stT = reinterpret_cast<float*>(sm);      // [128 cols][PT] transposed stage
        int lr0 = wm * 64 + tr;                         // local row (0..127)
#pragma unroll
        for (int mt = 0; mt < 4; mt++) {
            int r0 = lr0 + mt * 16, r1 = r0 + 8;
#pragma unroll
            for (int nt = 0; nt < 4; nt++) {
                int lc = wn * 32 + nt * 8 + tc;         // local col
                stT[lc * PT + r0]       = acc[mt][nt][0];
                stT[(lc + 1) * PT + r0] = acc[mt][nt][1];
                stT[lc * PT + r1]       = acc[mt][nt][2];
                stT[(lc + 1) * PT + r1] = acc[mt][nt][3];
            }
        }
        __syncthreads();
        bool fullR = (rb + 128 <= N_NODES);             // mirror cols = rb..rb+127
#pragma unroll
        for (int it = 0; it < 16; it++) {
            int j = wid + it * 8;                       // local mirror row
            int gr = cb + j;
            if (gr < N_NODES) {
                float4 v = *reinterpret_cast<const float4*>(stT + j * PT + lane * 4);
                float* p = out + (size_t)gr * N_NODES + rb + lane * 4;
                if (fullR) {
                    *reinterpret_cast<float4*>(p) = v;
                } else {
                    int c0 = rb + lane * 4;
                    if (c0 + 0 < N_NODES) p[0] = v.x;
                    if (c0 + 1 < N_NODES) p[1] = v.y;
                    if (c0 + 2 < N_NODES) p[2] = v.z;
                    if (c0 + 3 < N_NODES) p[3] = v.w;
                }
            }
        }
    }
}

// ---------------- launch ----------------
extern "C" void kernel_launch(void* const* d_in, const int* in_sizes, int n_in,
                              void* d_out, int out_size) {
    const float* x     = (const float*)d_in[0];
    const int*   ei    = (const int*)  d_in[1];
    const float* ew    = (const float*)d_in[2];
    const float* noise = (const float*)d_in[3];
    const float* W1    = (const float*)d_in[4];
    const float* b1    = (const float*)d_in[5];
    const float* W2    = (const float*)d_in[6];
    const float* b2    = (const float*)d_in[7];
    const float* W3    = (const float*)d_in[8];
    const float* b3    = (const float*)d_in[9];
    float* out = (float*)d_out;

    static int smem_set = 0;
    if (!smem_set) {
        cudaFuncSetAttribute(k_decoder, cudaFuncAttributeMaxDynamicSharedMemorySize, DEC_SMEM);
        smem_set = 1;
    }

    k_prep     <<<40, 256>>>();                        // 0
    k_deg_edges<<<625, 256>>>(ei, ew);                 // 1
    k_offsets  <<<40, 256>>>();                        // 2
    k_scatter  <<<625, 256>>>(ei, ew);                 // 3  <- profiled
    k_gemm1    <<<313, 256>>>(x, W1);                  // 4
    k_agg      <<<1250, 256>>>(1, b1, b2, b3);         // 5
    k_gemm23   <<<313, 256>>>(W2, W3);                 // 6
    k_agg      <<<1250, 256>>>(2, b1, b2, b3);         // 7
    k_z        <<<(N_PAD * H2) / 256, 256>>>(noise);   // 8
    dim3 g(NT, NT);
    k_decoder  <<<g, 256, DEC_SMEM>>>(out);            // 9
}